// round 13
// baseline (speedup 1.0000x reference)
#include <cuda_runtime.h>
#include <cuda_fp16.h>
#include <cstdint>

#define NTH    256
#define D_IN   1024
#define D_OUT  4096
#define XN     (8192 * 1024)
#define WBN    (4096 * 1024)

__device__ __half g_xh[XN];           // x  as fp16
__device__ __half g_wbh[WBN];         // Wb as fp16
__device__ __half g_w1img[64 * 8192]; // W1 pre-swizzled smem images (16KB/seed)
__device__ __half g_w2img[64 * 8192]; // W2 pre-swizzled smem images

// ---------------- smem layout (bytes), CTA tile 64 x 128 ----------------
// phase 1: 3 staging buffers 24KB (x 8KB + wb 16KB each), k-tile=64
// phase 2 overlays staging (72KB region):
//   ysw fp16 [64][128] swz      0 .. 16383
//   h   fp16 [64][128] swz  16384 .. 32767
//   W   (W1 16KB + W2 16KB) 32768 .. 65535
//   bbs fp32 [128]           73728 .. 74239
#define BUF(i)   ((i) * 24576)
#define YSW_OFF  0
#define H_OFF    16384
#define W_OFF    32768
#define BBS_OFF  73728
#define SMEM_TOTAL 74240

__device__ __forceinline__ uint32_t h2u(__half2 h) {
    return *reinterpret_cast<uint32_t*>(&h);
}
__device__ __forceinline__ void cpa16(uint32_t dst, const void* src) {
    asm volatile("cp.async.cg.shared.global [%0], [%1], 16;"
                 :: "r"(dst), "l"(src) : "memory");
}
__device__ __forceinline__ void cp_commit() {
    asm volatile("cp.async.commit_group;" ::: "memory");
}
template <int N>
__device__ __forceinline__ void cp_wait() {
    asm volatile("cp.async.wait_group %0;" :: "n"(N) : "memory");
}
__device__ __forceinline__ void ldsm4(uint32_t& r0, uint32_t& r1, uint32_t& r2,
                                      uint32_t& r3, uint32_t addr) {
    asm volatile("ldmatrix.sync.aligned.m8n8.x4.shared.b16 {%0,%1,%2,%3}, [%4];"
                 : "=r"(r0), "=r"(r1), "=r"(r2), "=r"(r3) : "r"(addr));
}
__device__ __forceinline__ void mma16(float* c, const uint32_t* a, const uint32_t* b) {
    asm volatile("mma.sync.aligned.m16n8k16.row.col.f32.f16.f16.f32 "
                 "{%0,%1,%2,%3},{%4,%5,%6,%7},{%8,%9},{%0,%1,%2,%3};"
                 : "+f"(c[0]), "+f"(c[1]), "+f"(c[2]), "+f"(c[3])
                 : "r"(a[0]), "r"(a[1]), "r"(a[2]), "r"(a[3]),
                   "r"(b[0]), "r"(b[1]));
}

// ============== prep: fp16 conversions + pre-swizzled W images ==============
__global__ void prep_kernel(const float* __restrict__ x,  const float* __restrict__ Wb,
                            const float* __restrict__ W1, const float* __restrict__ W2)
{
    const int tid = blockIdx.x * blockDim.x + threadIdx.x;
    const int nth = gridDim.x * blockDim.x;

    for (int i = tid; i < XN / 8; i += nth) {
        const float4* src = (const float4*)x + (size_t)i * 2;
        float4 v0 = src[0], v1 = src[1];
        ((uint4*)g_xh)[i] = make_uint4(h2u(__floats2half2_rn(v0.x, v0.y)),
                                       h2u(__floats2half2_rn(v0.z, v0.w)),
                                       h2u(__floats2half2_rn(v1.x, v1.y)),
                                       h2u(__floats2half2_rn(v1.z, v1.w)));
    }
    for (int i = tid; i < WBN / 8; i += nth) {
        const float4* src = (const float4*)Wb + (size_t)i * 2;
        float4 v0 = src[0], v1 = src[1];
        ((uint4*)g_wbh)[i] = make_uint4(h2u(__floats2half2_rn(v0.x, v0.y)),
                                        h2u(__floats2half2_rn(v0.z, v0.w)),
                                        h2u(__floats2half2_rn(v1.x, v1.y)),
                                        h2u(__floats2half2_rn(v1.z, v1.w)));
    }
    // W1 [s][c][h] -> image [h][c] swizzled; 8 c-values per 16B store.
    for (int i = tid; i < 64 * 1024; i += nth) {
        int s = i >> 10, c8 = (i >> 7) & 7, h = i & 127;
        const float* src = W1 + (((size_t)s * 64 + c8 * 8) * 128 + h);
        uint32_t p[4];
        #pragma unroll
        for (int j = 0; j < 4; j++)
            p[j] = h2u(__floats2half2_rn(src[(2*j) * 128], src[(2*j+1) * 128]));
        int off = h * 64 + ((c8 ^ (h & 7)) << 3);
        *(uint4*)(g_w1img + (size_t)s * 8192 + off) = make_uint4(p[0], p[1], p[2], p[3]);
    }
    // W2 [s][h][c] -> image [c][h] swizzled; 8 h-values per 16B store.
    for (int i = tid; i < 64 * 1024; i += nth) {
        int s = i >> 10, h8 = (i >> 6) & 15, c = i & 63;
        const float* src = W2 + (((size_t)s * 128 + h8 * 8) * 64 + c);
        uint32_t p[4];
        #pragma unroll
        for (int j = 0; j < 4; j++)
            p[j] = h2u(__floats2half2_rn(src[(2*j) * 64], src[(2*j+1) * 64]));
        int off = c * 128 + ((h8 ^ (c & 7)) << 3);
        *(uint4*)(g_w2img + (size_t)s * 8192 + off) = make_uint4(p[0], p[1], p[2], p[3]);
    }
}

// stage one k-tile (k=64): x[64x64]h (8KB) + wb[128x64]h (16KB), 128B rows
__device__ __forceinline__ void issue_tile(uint32_t su, const __half* xg,
                                           const __half* wbg, int kt, int b, int tid)
{
    const int k0 = kt * 64;
    #pragma unroll
    for (int i = 0; i < 2; i++) {
        int idx = tid + i * NTH;          // 0..511
        int r = idx >> 3, c4 = idx & 7;
        cpa16(su + BUF(b) + r * 128 + ((c4 ^ (r & 7)) << 4),
              xg + (size_t)r * D_IN + k0 + c4 * 8);
    }
    #pragma unroll
    for (int i = 0; i < 4; i++) {
        int idx = tid + i * NTH;          // 0..1023
        int n = idx >> 3, c4 = idx & 7;
        cpa16(su + BUF(b) + 8192 + n * 128 + ((c4 ^ (n & 7)) << 4),
              wbg + (size_t)n * D_IN + k0 + c4 * 8);
    }
}

// 16KB image loads (1024 x 16B chunks, 4 per thread)
__device__ __forceinline__ void issue_w1(uint32_t su, int sg, int tid) {
    const __half* src = g_w1img + (size_t)sg * 8192;
    #pragma unroll
    for (int i = 0; i < 4; i++) {
        int c = tid + i * NTH;
        cpa16(su + W_OFF + c * 16, src + c * 8);
    }
}
__device__ __forceinline__ void issue_w2(uint32_t su, int sg, int tid) {
    const __half* src = g_w2img + (size_t)sg * 8192;
    #pragma unroll
    for (int i = 0; i < 4; i++) {
        int c = tid + i * NTH;
        cpa16(su + W_OFF + 16384 + c * 16, src + c * 8);
    }
}

__global__ __launch_bounds__(NTH, 3)
void kasmina_main_kernel(const float* __restrict__ bb,
                         const float* __restrict__ b1,
                         const float* __restrict__ b2,
                         const float* __restrict__ alpha,
                         const int*   __restrict__ active,
                         float* __restrict__ out)
{
    extern __shared__ char smem[];
    const uint32_t su = (uint32_t)__cvta_generic_to_shared(smem);
    float* bbs = (float*)(smem + BBS_OFF);

    const int bx   = blockIdx.x;          // out cols [bx*128, bx*128+128)
    const int row0 = blockIdx.y * 64;     // 64-row tile

    const int tid    = threadIdx.x;
    const int lane   = tid & 31;
    const int wid    = tid >> 5;
    const int warp_m = wid & 1;           // 32-row half
    const int warp_n = wid >> 1;          // 32-col quarter

    const __half* xg  = g_xh  + (size_t)row0 * D_IN;
    const __half* wbg = g_wbh + (size_t)(bx * 128) * D_IN;

    if (tid < 128) bbs[tid] = bb[bx * 128 + tid];

    const float aw0 = alpha[bx * 2]     * (active[bx * 2]     != 0 ? 1.f : 0.f);
    const float aw1 = alpha[bx * 2 + 1] * (active[bx * 2 + 1] != 0 ? 1.f : 0.f);

    // prologue: tiles 0,1
    issue_tile(su, xg, wbg, 0, 0, tid);  cp_commit();
    issue_tile(su, xg, wbg, 1, 1, tid);  cp_commit();

    // ================= base GEMM: 16 k-tiles, 3-buffer, 1 barrier/tile =================
    // PROVEN ORDERING (r8): cp_wait -> __syncthreads -> issue next.
    float acc[2][4][4];
    #pragma unroll
    for (int mt = 0; mt < 2; mt++)
        #pragma unroll
        for (int nt = 0; nt < 4; nt++)
            #pragma unroll
            for (int q = 0; q < 4; q++) acc[mt][nt][q] = 0.f;

    int bc = 0, bw = 2;
    #pragma unroll 1
    for (int ks = 0; ks < 16; ks++) {
        cp_wait<1>();      // this thread's share of tile ks landed
        __syncthreads();   // all threads' waits done; write-buf readers drained
        if (ks + 2 < 16) issue_tile(su, xg, wbg, ks + 2, bw, tid);
        cp_commit();

        const uint32_t xs  = su + BUF(bc);
        const uint32_t wbs = xs + 8192;
        #pragma unroll
        for (int kk = 0; kk < 4; kk++) {
            uint32_t a[2][4], b[4][2];
            #pragma unroll
            for (int mt = 0; mt < 2; mt++) {
                int row = warp_m * 32 + mt * 16 + ((lane >> 3) & 1) * 8 + (lane & 7);
                int ch  = kk * 2 + (lane >> 4);
                ldsm4(a[mt][0], a[mt][1], a[mt][2], a[mt][3],
                      xs + row * 128 + ((ch ^ (row & 7)) << 4));
            }
            #pragma unroll
            for (int p = 0; p < 2; p++) {
                int row = warp_n * 32 + p * 16 + (lane >> 4) * 8 + (lane & 7);
                int ch  = kk * 2 + ((lane >> 3) & 1);
                ldsm4(b[2*p][0], b[2*p][1], b[2*p+1][0], b[2*p+1][1],
                      wbs + row * 128 + ((ch ^ (row & 7)) << 4));
            }
            #pragma unroll
            for (int mt = 0; mt < 2; mt++)
                #pragma unroll
                for (int nt = 0; nt < 4; nt++)
                    mma16(acc[mt][nt], a[mt], b[nt]);
        }
        bc = (bc == 2) ? 0 : bc + 1;
        bw = (bw == 2) ? 0 : bw + 1;
    }
    __syncthreads();   // all warps past compute(15); staging free for reuse

    // prefetch W images for the FIRST ACTIVE seed only (uniform per CTA)
    const int first_act = (aw0 != 0.f) ? 0 : ((aw1 != 0.f) ? 1 : -1);
    if (first_act >= 0) {
        issue_w1(su, bx * 2 + first_act, tid);
        issue_w2(su, bx * 2 + first_act, tid);
        cp_commit();
    }

    // epilogue (sl = warp_n>>1, UNIFORM per warp):
    //   active   -> y+bb fp16 into ysw ; inactive -> y+bb fp32 direct to out
    {
        const int  sl_w  = warp_n >> 1;
        const bool act_w = (sl_w == 0) ? (aw0 != 0.f) : (aw1 != 0.f);
        #pragma unroll
        for (int mt = 0; mt < 2; mt++) {
            #pragma unroll
            for (int nt = 0; nt < 4; nt++) {
                int c0 = warp_n * 32 + nt * 8 + 2 * (lane & 3);
                int r0 = warp_m * 32 + mt * 16 + (lane >> 2);
                float bx0 = bbs[c0], bx1 = bbs[c0 + 1];
                float v00 = acc[mt][nt][0] + bx0, v01 = acc[mt][nt][1] + bx1;
                float v10 = acc[mt][nt][2] + bx0, v11 = acc[mt][nt][3] + bx1;
                if (act_w) {
                    uint32_t sw0 = (((c0 >> 3) ^ (r0 & 7)) << 4) + ((c0 * 2) & 15);
                    uint32_t sw1 = (((c0 >> 3) ^ ((r0 + 8) & 7)) << 4) + ((c0 * 2) & 15);
                    *(uint32_t*)(smem + YSW_OFF + r0 * 256 + sw0) =
                        h2u(__floats2half2_rn(v00, v01));
                    *(uint32_t*)(smem + YSW_OFF + (r0 + 8) * 256 + sw1) =
                        h2u(__floats2half2_rn(v10, v11));
                } else {
                    *(float2*)&out[(size_t)(row0 + r0) * D_OUT + bx * 128 + c0] =
                        make_float2(v00, v01);
                    *(float2*)&out[(size_t)(row0 + r0 + 8) * D_OUT + bx * 128 + c0] =
                        make_float2(v10, v11);
                }
            }
        }
    }
    if (first_act < 0) return;   // both seeds inactive (uniform)

    cp_wait<0>();
    __syncthreads();   // ysw + first W visible everywhere

    const uint32_t ysw_b = su + YSW_OFF;
    const uint32_t h_b   = su + H_OFF;
    const uint32_t w1b   = su + W_OFF;
    const uint32_t w2b   = su + W_OFF + 16384;

    // ================= per-seed MLP + blend (active seeds only) =================
    #pragma unroll 1
    for (int sl = 0; sl < 2; sl++) {
        const float aw = (sl == 0) ? aw0 : aw1;
        if (aw == 0.f) continue;                 // uniform per CTA
        const int   sg  = bx * 2 + sl;
        const float omw = 1.f - aw;

        if (sl == 1 && aw0 != 0.f) {   // seed-1 W issued during seed-0 stage B
            cp_wait<0>();
            __syncthreads();
        }

        // ---- stage A: h = relu(y @ W1 + b1)   M=64 N=128 K=64 ----
        {
            float accA[2][4][4];
            #pragma unroll
            for (int mt = 0; mt < 2; mt++)
                #pragma unroll
                for (int nt = 0; nt < 4; nt++)
                    #pragma unroll
                    for (int q = 0; q < 4; q++) accA[mt][nt][q] = 0.f;

            #pragma unroll
            for (int kk = 0; kk < 4; kk++) {
                uint32_t a[2][4], b[4][2];
                #pragma unroll
                for (int mt = 0; mt < 2; mt++) {
                    int row = warp_m * 32 + mt * 16 + ((lane >> 3) & 1) * 8 + (lane & 7);
                    int ch  = sl * 8 + kk * 2 + (lane >> 4);
                    ldsm4(a[mt][0], a[mt][1], a[mt][2], a[mt][3],
                          ysw_b + row * 256 + ((ch ^ (row & 7)) << 4));
                }
                #pragma unroll
                for (int p = 0; p < 2; p++) {
                    int row = warp_n * 32 + p * 16 + (lane >> 4) * 8 + (lane & 7);
                    int ch  = kk * 2 + ((lane >> 3) & 1);
                    ldsm4(b[2*p][0], b[2*p][1], b[2*p+1][0], b[2*p+1][1],
                          w1b + row * 128 + ((ch ^ (row & 7)) << 4));
                }
                #pragma unroll
                for (int mt = 0; mt < 2; mt++)
                    #pragma unroll
                    for (int nt = 0; nt < 4; nt++)
                        mma16(accA[mt][nt], a[mt], b[nt]);
            }

            // bias + relu -> h (fp16 swizzled)
            #pragma unroll
            for (int mt = 0; mt < 2; mt++) {
                #pragma unroll
                for (int nt = 0; nt < 4; nt++) {
                    int h0 = warp_n * 32 + nt * 8 + 2 * (lane & 3);
                    int r0 = warp_m * 32 + mt * 16 + (lane >> 2);
                    float2 b1v = *(const float2*)&b1[sg * 128 + h0];
                    float v0 = fmaxf(accA[mt][nt][0] + b1v.x, 0.f);
                    float v1 = fmaxf(accA[mt][nt][1] + b1v.y, 0.f);
                    float v2 = fmaxf(accA[mt][nt][2] + b1v.x, 0.f);
                    float v3 = fmaxf(accA[mt][nt][3] + b1v.y, 0.f);
                    uint32_t sw0 = (((h0 >> 3) ^ (r0 & 7)) << 4) + ((h0 * 2) & 15);
                    uint32_t sw1 = (((h0 >> 3) ^ ((r0 + 8) & 7)) << 4) + ((h0 * 2) & 15);
                    *(uint32_t*)(smem + H_OFF + r0 * 256 + sw0) =
                        h2u(__floats2half2_rn(v0, v1));
                    *(uint32_t*)(smem + H_OFF + (r0 + 8) * 256 + sw1) =
                        h2u(__floats2half2_rn(v2, v3));
                }
            }
        }
        __syncthreads();   // h visible

        // ---- stage B: bp = h @ W2 + b2; blend with fp16 y; store ----
        {
            float accB[2][2][4];
            #pragma unroll
            for (int mt = 0; mt < 2; mt++)
                #pragma unroll
                for (int nt = 0; nt < 2; nt++)
                    #pragma unroll
                    for (int q = 0; q < 4; q++) accB[mt][nt][q] = 0.f;

            #pragma unroll 2
            for (int kk = 0; kk < 8; kk++) {
                uint32_t a[2][4], b[2][2];
                #pragma unroll
                for (int mt = 0; mt < 2; mt++) {
                    int row = warp_m * 32 + mt * 16 + ((lane >> 3) & 1) * 8 + (lane & 7);
                    int ch  = kk * 2 + (lane >> 4);
                    ldsm4(a[mt][0], a[mt][1], a[mt][2], a[mt][3],
                          h_b + row * 256 + ((ch ^ (row & 7)) << 4));
                }
                {
                    int row = warp_n * 16 + (lane >> 4) * 8 + (lane & 7);
                    int ch  = kk * 2 + ((lane >> 3) & 1);
                    ldsm4(b[0][0], b[0][1], b[1][0], b[1][1],
                          w2b + row * 256 + ((ch ^ (row & 7)) << 4));
                }
                #pragma unroll
                for (int mt = 0; mt < 2; mt++)
                    #pragma unroll
                    for (int nt = 0; nt < 2; nt++)
                        mma16(accB[mt][nt], a[mt], b[nt]);
            }

            #pragma unroll
            for (int mt = 0; mt < 2; mt++) {
                #pragma unroll
                for (int nt = 0; nt < 2; nt++) {
                    int c0 = warp_n * 16 + nt * 8 + 2 * (lane & 3);
                    int cy = sl * 64 + c0;
                    int r0 = warp_m * 32 + mt * 16 + (lane >> 2);
                    float2 b2v = *(const float2*)&b2[sg * 64 + c0];

                    __half2 hy0 = *(const __half2*)(smem + YSW_OFF + r0 * 256 +
                                   (((cy >> 3) ^ (r0 & 7)) << 4) + ((cy * 2) & 15));
                    float2 y0 = __half22float2(hy0);
                    *(float2*)&out[(size_t)(row0 + r0) * D_OUT + bx * 128 + cy] =
                        make_float2(omw * y0.x + aw * (accB[mt][nt][0] + b2v.x),
                                    omw * y0.y + aw * (accB[mt][nt][1] + b2v.y));

                    __half2 hy1 = *(const __half2*)(smem + YSW_OFF + (r0 + 8) * 256 +
                                   (((cy >> 3) ^ ((r0 + 8) & 7)) << 4) + ((cy * 2) & 15));
                    float2 y1 = __half22float2(hy1);
                    *(float2*)&out[(size_t)(row0 + r0 + 8) * D_OUT + bx * 128 + cy] =
                        make_float2(omw * y1.x + aw * (accB[mt][nt][2] + b2v.x),
                                    omw * y1.y + aw * (accB[mt][nt][3] + b2v.y));
                }
            }
        }

        if (sl == 0 && aw1 != 0.f) {   // uniform; prefetch seed-1 W images
            __syncthreads();           // W/h reads complete before overwrite
            issue_w1(su, sg + 1, tid);
            issue_w2(su, sg + 1, tid);
            cp_commit();
        }
    }
}

extern "C" void kernel_launch(void* const* d_in, const int* in_sizes, int n_in,
                              void* d_out, int out_size)
{
    const float* x      = (const float*)d_in[0];
    const float* Wb     = (const float*)d_in[1];
    const float* bb     = (const float*)d_in[2];
    const float* W1     = (const float*)d_in[3];
    const float* b1     = (const float*)d_in[4];
    const float* W2     = (const float*)d_in[5];
    const float* b2     = (const float*)d_in[6];
    const float* alpha  = (const float*)d_in[7];
    const int*   active = (const int*)d_in[8];
    float* out = (float*)d_out;

    prep_kernel<<<1024, 256>>>(x, Wb, W1, W2);

    cudaFuncSetAttribute(kasmina_main_kernel,
                         cudaFuncAttributeMaxDynamicSharedMemorySize, SMEM_TOTAL);
    dim3 grid(32, 128);   // (seed pairs, 64-row blocks)
    kasmina_main_kernel<<<grid, NTH, SMEM_TOTAL>>>(
        bb, b1, b2, alpha, active, out);
}

// round 14
// speedup vs baseline: 1.0675x; 1.0675x over previous
#include <cuda_runtime.h>
#include <cuda_fp16.h>
#include <cstdint>

#define NTH    256
#define D_IN   1024
#define D_OUT  4096
#define XN     (8192 * 1024)
#define WBN    (4096 * 1024)

__device__ __half g_xh[XN];           // x  as fp16
__device__ __half g_wbh[WBN];         // Wb as fp16
__device__ __half g_w1img[64 * 8192]; // W1 pre-swizzled smem images (16KB/seed)
__device__ __half g_w2img[64 * 8192]; // W2 pre-swizzled smem images

// ---------------- smem layout (bytes), CTA tile 128 x 128 (r12 proven) ----------------
// phase 1: 3 staging buffers 32KB (x 16KB + wb 16KB each), k-tile=64
// phase 2 overlays staging:
//   ysw fp16 [128][128] swz  buf0:      0 .. 32767
//   h   fp16 [128][128] swz  buf1:  32768 .. 65535
//   W   (W1 16KB + W2 16KB)  buf2:  65536 .. 98303
//   bbs fp32 [128]                  98304 .. 98815
#define BUF(i)   ((i) * 32768)
#define YSW_OFF  0
#define H_OFF    32768
#define W_OFF    65536
#define BBS_OFF  98304
#define SMEM_TOTAL 98816

__device__ __forceinline__ uint32_t h2u(__half2 h) {
    return *reinterpret_cast<uint32_t*>(&h);
}
__device__ __forceinline__ void cpa16(uint32_t dst, const void* src) {
    asm volatile("cp.async.cg.shared.global [%0], [%1], 16;"
                 :: "r"(dst), "l"(src) : "memory");
}
__device__ __forceinline__ void cp_commit() {
    asm volatile("cp.async.commit_group;" ::: "memory");
}
template <int N>
__device__ __forceinline__ void cp_wait() {
    asm volatile("cp.async.wait_group %0;" :: "n"(N) : "memory");
}
__device__ __forceinline__ void ldsm4(uint32_t& r0, uint32_t& r1, uint32_t& r2,
                                      uint32_t& r3, uint32_t addr) {
    asm volatile("ldmatrix.sync.aligned.m8n8.x4.shared.b16 {%0,%1,%2,%3}, [%4];"
                 : "=r"(r0), "=r"(r1), "=r"(r2), "=r"(r3) : "r"(addr));
}
__device__ __forceinline__ void mma16(float* c, const uint32_t* a, const uint32_t* b) {
    asm volatile("mma.sync.aligned.m16n8k16.row.col.f32.f16.f16.f32 "
                 "{%0,%1,%2,%3},{%4,%5,%6,%7},{%8,%9},{%0,%1,%2,%3};"
                 : "+f"(c[0]), "+f"(c[1]), "+f"(c[2]), "+f"(c[3])
                 : "r"(a[0]), "r"(a[1]), "r"(a[2]), "r"(a[3]),
                   "r"(b[0]), "r"(b[1]));
}

// ============== prep: fp16 conversions + pre-swizzled W images ==============
__global__ void prep_kernel(const float* __restrict__ x,  const float* __restrict__ Wb,
                            const float* __restrict__ W1, const float* __restrict__ W2)
{
    const int tid = blockIdx.x * blockDim.x + threadIdx.x;
    const int nth = gridDim.x * blockDim.x;

    for (int i = tid; i < XN / 8; i += nth) {
        const float4* src = (const float4*)x + (size_t)i * 2;
        float4 v0 = src[0], v1 = src[1];
        ((uint4*)g_xh)[i] = make_uint4(h2u(__floats2half2_rn(v0.x, v0.y)),
                                       h2u(__floats2half2_rn(v0.z, v0.w)),
                                       h2u(__floats2half2_rn(v1.x, v1.y)),
                                       h2u(__floats2half2_rn(v1.z, v1.w)));
    }
    for (int i = tid; i < WBN / 8; i += nth) {
        const float4* src = (const float4*)Wb + (size_t)i * 2;
        float4 v0 = src[0], v1 = src[1];
        ((uint4*)g_wbh)[i] = make_uint4(h2u(__floats2half2_rn(v0.x, v0.y)),
                                        h2u(__floats2half2_rn(v0.z, v0.w)),
                                        h2u(__floats2half2_rn(v1.x, v1.y)),
                                        h2u(__floats2half2_rn(v1.z, v1.w)));
    }
    // W1 [s][c][h] -> image [h][c] swizzled; 8 c-values per 16B store.
    for (int i = tid; i < 64 * 1024; i += nth) {
        int s = i >> 10, c8 = (i >> 7) & 7, h = i & 127;
        const float* src = W1 + (((size_t)s * 64 + c8 * 8) * 128 + h);
        uint32_t p[4];
        #pragma unroll
        for (int j = 0; j < 4; j++)
            p[j] = h2u(__floats2half2_rn(src[(2*j) * 128], src[(2*j+1) * 128]));
        int off = h * 64 + ((c8 ^ (h & 7)) << 3);
        *(uint4*)(g_w1img + (size_t)s * 8192 + off) = make_uint4(p[0], p[1], p[2], p[3]);
    }
    // W2 [s][h][c] -> image [c][h] swizzled; 8 h-values per 16B store.
    for (int i = tid; i < 64 * 1024; i += nth) {
        int s = i >> 10, h8 = (i >> 6) & 15, c = i & 63;
        const float* src = W2 + (((size_t)s * 128 + h8 * 8) * 64 + c);
        uint32_t p[4];
        #pragma unroll
        for (int j = 0; j < 4; j++)
            p[j] = h2u(__floats2half2_rn(src[(2*j) * 64], src[(2*j+1) * 64]));
        int off = c * 128 + ((h8 ^ (c & 7)) << 3);
        *(uint4*)(g_w2img + (size_t)s * 8192 + off) = make_uint4(p[0], p[1], p[2], p[3]);
    }
}

// stage one k-tile (k=64): x[128x64]h + wb[128x64]h, both 16KB, 128B rows
__device__ __forceinline__ void issue_tile(uint32_t su, const __half* xg,
                                           const __half* wbg, int kt, int b, int tid)
{
    const int k0 = kt * 64;
    #pragma unroll
    for (int i = 0; i < 4; i++) {
        int idx = tid + i * NTH;
        int r = idx >> 3, c4 = idx & 7;
        cpa16(su + BUF(b) + r * 128 + ((c4 ^ (r & 7)) << 4),
              xg + (size_t)r * D_IN + k0 + c4 * 8);
    }
    #pragma unroll
    for (int i = 0; i < 4; i++) {
        int idx = tid + i * NTH;
        int n = idx >> 3, c4 = idx & 7;
        cpa16(su + BUF(b) + 16384 + n * 128 + ((c4 ^ (n & 7)) << 4),
              wbg + (size_t)n * D_IN + k0 + c4 * 8);
    }
}

// 16KB image loads (1024 x 16B chunks, 4 per thread)
__device__ __forceinline__ void issue_w1(uint32_t su, int sg, int tid) {
    const __half* src = g_w1img + (size_t)sg * 8192;
    #pragma unroll
    for (int i = 0; i < 4; i++) {
        int c = tid + i * NTH;
        cpa16(su + W_OFF + c * 16, src + c * 8);
    }
}
__device__ __forceinline__ void issue_w2(uint32_t su, int sg, int tid) {
    const __half* src = g_w2img + (size_t)sg * 8192;
    #pragma unroll
    for (int i = 0; i < 4; i++) {
        int c = tid + i * NTH;
        cpa16(su + W_OFF + 16384 + c * 16, src + c * 8);
    }
}

__global__ __launch_bounds__(NTH, 2)
void kasmina_main_kernel(const float* __restrict__ bb,
                         const float* __restrict__ b1,
                         const float* __restrict__ b2,
                         const float* __restrict__ alpha,
                         const int*   __restrict__ active,
                         float* __restrict__ out)
{
    extern __shared__ char smem[];
    const uint32_t su = (uint32_t)__cvta_generic_to_shared(smem);
    float* bbs = (float*)(smem + BBS_OFF);

    const int bx   = blockIdx.x;          // out cols [bx*128, bx*128+128)
    const int row0 = blockIdx.y * 128;

    const int tid    = threadIdx.x;
    const int lane   = tid & 31;
    const int wid    = tid >> 5;
    const int warp_m = wid & 1;
    const int warp_n = wid >> 1;

    const __half* xg  = g_xh  + (size_t)row0 * D_IN;
    const __half* wbg = g_wbh + (size_t)(bx * 128) * D_IN;

    if (tid < 128) bbs[tid] = bb[bx * 128 + tid];

    // per-CTA-uniform blend weights
    const float aw0 = alpha[bx * 2]     * (active[bx * 2]     != 0 ? 1.f : 0.f);
    const float aw1 = alpha[bx * 2 + 1] * (active[bx * 2 + 1] != 0 ? 1.f : 0.f);
    const int first_act = (aw0 != 0.f) ? 0 : ((aw1 != 0.f) ? 1 : -1);

    // prologue: tiles 0,1
    issue_tile(su, xg, wbg, 0, 0, tid);  cp_commit();
    issue_tile(su, xg, wbg, 1, 1, tid);  cp_commit();

    // ================= base GEMM: 16 k-tiles, 3-buffer, 1 barrier/tile =================
    // PROVEN ORDERING (r8): cp_wait -> __syncthreads -> issue next.
    float acc[4][4][4];
    #pragma unroll
    for (int mt = 0; mt < 4; mt++)
        #pragma unroll
        for (int nt = 0; nt < 4; nt++)
            #pragma unroll
            for (int q = 0; q < 4; q++) acc[mt][nt][q] = 0.f;

    int bc = 0, bw = 2;   // compute buf, write buf (mod-3 counters)
    #pragma unroll 1
    for (int ks = 0; ks < 16; ks++) {
        cp_wait<1>();      // this thread's share of tile ks landed
        __syncthreads();   // all threads' waits done -> tile ks visible to all;
                           // + every warp finished reading buf bw (iter ks-1)
        if (ks + 2 < 16) {
            issue_tile(su, xg, wbg, ks + 2, bw, tid);
        } else if (ks == 15 && first_act >= 0) {
            // buf2's staging readers drained at this iteration's barrier (bw==2):
            // stream first active seed's W images in; they overlap compute(15)
            // and the whole epilogue.
            issue_w1(su, bx * 2 + first_act, tid);
            issue_w2(su, bx * 2 + first_act, tid);
        }
        cp_commit();

        const uint32_t xs  = su + BUF(bc);
        const uint32_t wbs = xs + 16384;
        #pragma unroll
        for (int kk = 0; kk < 4; kk++) {
            uint32_t a[4][4], b[4][2];
            #pragma unroll
            for (int mt = 0; mt < 4; mt++) {
                int row = warp_m * 64 + mt * 16 + ((lane >> 3) & 1) * 8 + (lane & 7);
                int ch  = kk * 2 + (lane >> 4);
                ldsm4(a[mt][0], a[mt][1], a[mt][2], a[mt][3],
                      xs + row * 128 + ((ch ^ (row & 7)) << 4));
            }
            #pragma unroll
            for (int p = 0; p < 2; p++) {
                int row = warp_n * 32 + p * 16 + (lane >> 4) * 8 + (lane & 7);
                int ch  = kk * 2 + ((lane >> 3) & 1);
                ldsm4(b[2*p][0], b[2*p][1], b[2*p+1][0], b[2*p+1][1],
                      wbs + row * 128 + ((ch ^ (row & 7)) << 4));
            }
            #pragma unroll
            for (int mt = 0; mt < 4; mt++)
                #pragma unroll
                for (int nt = 0; nt < 4; nt++)
                    mma16(acc[mt][nt], a[mt], b[nt]);
        }
        bc = (bc == 2) ? 0 : bc + 1;
        bw = (bw == 2) ? 0 : bw + 1;
    }
    __syncthreads();   // all warps past compute(15); buf0 free for ysw reuse

    // epilogue: per seed-half (sl = warp_n>>1, UNIFORM per warp):
    //   active   -> y+bb as fp16 into ysw (for stage A + blend)
    //   inactive -> y+bb stored fp32 DIRECTLY to out (exact passthrough)
    {
        const int  sl_w   = warp_n >> 1;
        const bool act_w  = (sl_w == 0) ? (aw0 != 0.f) : (aw1 != 0.f);
        #pragma unroll
        for (int mt = 0; mt < 4; mt++) {
            #pragma unroll
            for (int nt = 0; nt < 4; nt++) {
                int c0 = warp_n * 32 + nt * 8 + 2 * (lane & 3);
                int r0 = warp_m * 64 + mt * 16 + (lane >> 2);
                float bx0 = bbs[c0], bx1 = bbs[c0 + 1];
                float v00 = acc[mt][nt][0] + bx0, v01 = acc[mt][nt][1] + bx1;
                float v10 = acc[mt][nt][2] + bx0, v11 = acc[mt][nt][3] + bx1;
                if (act_w) {
                    uint32_t sw0 = (((c0 >> 3) ^ (r0 & 7)) << 4) + ((c0 * 2) & 15);
                    uint32_t sw1 = (((c0 >> 3) ^ ((r0 + 8) & 7)) << 4) + ((c0 * 2) & 15);
                    *(uint32_t*)(smem + YSW_OFF + r0 * 256 + sw0) =
                        h2u(__floats2half2_rn(v00, v01));
                    *(uint32_t*)(smem + YSW_OFF + (r0 + 8) * 256 + sw1) =
                        h2u(__floats2half2_rn(v10, v11));
                } else {
                    *(float2*)&out[(size_t)(row0 + r0) * D_OUT + bx * 128 + c0] =
                        make_float2(v00, v01);
                    *(float2*)&out[(size_t)(row0 + r0 + 8) * D_OUT + bx * 128 + c0] =
                        make_float2(v10, v11);
                }
            }
        }
    }
    if (first_act < 0) return;   // both seeds inactive: CTA done (uniform)

    cp_wait<0>();      // first active seed's W images resident (issued at ks=15)
    __syncthreads();   // all threads' waits done; ysw + W visible everywhere

    const uint32_t ysw_b = su + YSW_OFF;
    const uint32_t h_b   = su + H_OFF;
    const uint32_t w1b   = su + W_OFF;
    const uint32_t w2b   = su + W_OFF + 16384;

    // ================= per-seed MLP + blend (active seeds only) =================
    #pragma unroll 1
    for (int sl = 0; sl < 2; sl++) {
        const float aw = (sl == 0) ? aw0 : aw1;
        if (aw == 0.f) continue;                 // uniform per CTA
        const int   sg  = bx * 2 + sl;
        const float omw = 1.f - aw;

        if (sl == 1 && aw0 != 0.f) {
            // W1(seed1) was issued after seed-0 stage A; W2(seed1) after stage B.
            cp_wait<1>();      // W1 resident (W2 group may still be in flight)
            __syncthreads();
        }

        // ---- stage A: h = relu(y @ W1 + b1)   M=128 N=128 K=64 ----
        {
            float accA[4][4][4];
            #pragma unroll
            for (int mt = 0; mt < 4; mt++)
                #pragma unroll
                for (int nt = 0; nt < 4; nt++)
                    #pragma unroll
                    for (int q = 0; q < 4; q++) accA[mt][nt][q] = 0.f;

            #pragma unroll
            for (int kk = 0; kk < 4; kk++) {
                uint32_t a[4][4], b[4][2];
                #pragma unroll
                for (int mt = 0; mt < 4; mt++) {
                    int row = warp_m * 64 + mt * 16 + ((lane >> 3) & 1) * 8 + (lane & 7);
                    int ch  = sl * 8 + kk * 2 + (lane >> 4);
                    ldsm4(a[mt][0], a[mt][1], a[mt][2], a[mt][3],
                          ysw_b + row * 256 + ((ch ^ (row & 7)) << 4));
                }
                #pragma unroll
                for (int p = 0; p < 2; p++) {
                    int row = warp_n * 32 + p * 16 + (lane >> 4) * 8 + (lane & 7);
                    int ch  = kk * 2 + ((lane >> 3) & 1);
                    ldsm4(b[2*p][0], b[2*p][1], b[2*p+1][0], b[2*p+1][1],
                          w1b + row * 128 + ((ch ^ (row & 7)) << 4));
                }
                #pragma unroll
                for (int mt = 0; mt < 4; mt++)
                    #pragma unroll
                    for (int nt = 0; nt < 4; nt++)
                        mma16(accA[mt][nt], a[mt], b[nt]);
            }

            // bias + relu -> h (fp16 swizzled, buf1)
            #pragma unroll
            for (int mt = 0; mt < 4; mt++) {
                #pragma unroll
                for (int nt = 0; nt < 4; nt++) {
                    int h0 = warp_n * 32 + nt * 8 + 2 * (lane & 3);
                    int r0 = warp_m * 64 + mt * 16 + (lane >> 2);
                    float2 b1v = *(const float2*)&b1[sg * 128 + h0];
                    float v0 = fmaxf(accA[mt][nt][0] + b1v.x, 0.f);
                    float v1 = fmaxf(accA[mt][nt][1] + b1v.y, 0.f);
                    float v2 = fmaxf(accA[mt][nt][2] + b1v.x, 0.f);
                    float v3 = fmaxf(accA[mt][nt][3] + b1v.y, 0.f);
                    uint32_t sw0 = (((h0 >> 3) ^ (r0 & 7)) << 4) + ((h0 * 2) & 15);
                    uint32_t sw1 = (((h0 >> 3) ^ ((r0 + 8) & 7)) << 4) + ((h0 * 2) & 15);
                    *(uint32_t*)(smem + H_OFF + r0 * 256 + sw0) =
                        h2u(__floats2half2_rn(v0, v1));
                    *(uint32_t*)(smem + H_OFF + (r0 + 8) * 256 + sw1) =
                        h2u(__floats2half2_rn(v2, v3));
                }
            }
        }
        if (sl == 1 && aw0 != 0.f) cp_wait<0>();   // W2(seed1) resident
        __syncthreads();   // h visible; W1-slot reads complete

        if (sl == 0 && aw1 != 0.f) {   // W1 slot dead from here: stream seed-1 W1
            issue_w1(su, sg + 1, tid);
            cp_commit();
        }

        // ---- stage B: bp = h @ W2 + b2; blend with fp16 y; store ----
        {
            float accB[4][2][4];
            #pragma unroll
            for (int mt = 0; mt < 4; mt++)
                #pragma unroll
                for (int nt = 0; nt < 2; nt++)
                    #pragma unroll
                    for (int q = 0; q < 4; q++) accB[mt][nt][q] = 0.f;

            #pragma unroll 2
            for (int kk = 0; kk < 8; kk++) {
                uint32_t a[4][4], b[2][2];
                #pragma unroll
                for (int mt = 0; mt < 4; mt++) {
                    int row = warp_m * 64 + mt * 16 + ((lane >> 3) & 1) * 8 + (lane & 7);
                    int ch  = kk * 2 + (lane >> 4);
                    ldsm4(a[mt][0], a[mt][1], a[mt][2], a[mt][3],
                          h_b + row * 256 + ((ch ^ (row & 7)) << 4));
                }
                {
                    int row = warp_n * 16 + (lane >> 4) * 8 + (lane & 7);
                    int ch  = kk * 2 + ((lane >> 3) & 1);
                    ldsm4(b[0][0], b[0][1], b[1][0], b[1][1],
                          w2b + row * 256 + ((ch ^ (row & 7)) << 4));
                }
                #pragma unroll
                for (int mt = 0; mt < 4; mt++)
                    #pragma unroll
                    for (int nt = 0; nt < 2; nt++)
                        mma16(accB[mt][nt], a[mt], b[nt]);
            }

            #pragma unroll
            for (int mt = 0; mt < 4; mt++) {
                #pragma unroll
                for (int nt = 0; nt < 2; nt++) {
                    int c0 = warp_n * 16 + nt * 8 + 2 * (lane & 3);
                    int cy = sl * 64 + c0;
                    int r0 = warp_m * 64 + mt * 16 + (lane >> 2);
                    float2 b2v = *(const float2*)&b2[sg * 64 + c0];

                    __half2 hy0 = *(const __half2*)(smem + YSW_OFF + r0 * 256 +
                                   (((cy >> 3) ^ (r0 & 7)) << 4) + ((cy * 2) & 15));
                    float2 y0 = __half22float2(hy0);
                    *(float2*)&out[(size_t)(row0 + r0) * D_OUT + bx * 128 + cy] =
                        make_float2(omw * y0.x + aw * (accB[mt][nt][0] + b2v.x),
                                    omw * y0.y + aw * (accB[mt][nt][1] + b2v.y));

                    __half2 hy1 = *(const __half2*)(smem + YSW_OFF + (r0 + 8) * 256 +
                                   (((cy >> 3) ^ ((r0 + 8) & 7)) << 4) + ((cy * 2) & 15));
                    float2 y1 = __half22float2(hy1);
                    *(float2*)&out[(size_t)(row0 + r0 + 8) * D_OUT + bx * 128 + cy] =
                        make_float2(omw * y1.x + aw * (accB[mt][nt][2] + b2v.x),
                                    omw * y1.y + aw * (accB[mt][nt][3] + b2v.y));
                }
            }
        }

        if (sl == 0 && aw1 != 0.f) {   // W2 slot dead after stage B reads drain
            __syncthreads();           // W2/h reads complete before overwrite
            issue_w2(su, sg + 1, tid);
            cp_commit();
        }
    }
}

extern "C" void kernel_launch(void* const* d_in, const int* in_sizes, int n_in,
                              void* d_out, int out_size)
{
    const float* x      = (const float*)d_in[0];
    const float* Wb     = (const float*)d_in[1];
    const float* bb     = (const float*)d_in[2];
    const float* W1     = (const float*)d_in[3];
    const float* b1     = (const float*)d_in[4];
    const float* W2     = (const float*)d_in[5];
    const float* b2     = (const float*)d_in[6];
    const float* alpha  = (const float*)d_in[7];
    const int*   active = (const int*)d_in[8];
    float* out = (float*)d_out;

    prep_kernel<<<1024, 256>>>(x, Wb, W1, W2);

    cudaFuncSetAttribute(kasmina_main_kernel,
                         cudaFuncAttributeMaxDynamicSharedMemorySize, SMEM_TOTAL);
    dim3 grid(32, 64);
    kasmina_main_kernel<<<grid, NTH, SMEM_TOTAL>>>(
        bb, b1, b2, alpha, active, out);
}

// round 15
// speedup vs baseline: 1.0902x; 1.0213x over previous
#include <cuda_runtime.h>
#include <cuda_fp16.h>
#include <cstdint>

#define NTH    256
#define D_IN   1024
#define D_OUT  4096
#define XN     (8192 * 1024)
#define WBN    (4096 * 1024)

__device__ __half g_xh[XN];           // x  as fp16
__device__ __half g_wbh[WBN];         // Wb as fp16
__device__ __half g_w1img[64 * 8192]; // W1 pre-swizzled smem images (16KB/seed)
__device__ __half g_w2img[64 * 8192]; // W2 pre-swizzled smem images

// ---------------- smem layout (bytes), CTA tile 128 x 128 (r12 proven) ----------------
// phase 1: 3 staging buffers 32KB (x 16KB + wb 16KB each), k-tile=64
// phase 2 overlays staging:
//   ysw fp16 [128][128] swz  buf0:      0 .. 32767
//   h   fp16 [128][128] swz  buf1:  32768 .. 65535
//   W   (W1 16KB + W2 16KB)  buf2:  65536 .. 98303
//   bbs fp32 [128]                  98304 .. 98815
#define BUF(i)   ((i) * 32768)
#define YSW_OFF  0
#define H_OFF    32768
#define W_OFF    65536
#define BBS_OFF  98304
#define SMEM_TOTAL 98816

__device__ __forceinline__ uint32_t h2u(__half2 h) {
    return *reinterpret_cast<uint32_t*>(&h);
}
__device__ __forceinline__ void cpa16(uint32_t dst, const void* src) {
    asm volatile("cp.async.cg.shared.global [%0], [%1], 16;"
                 :: "r"(dst), "l"(src) : "memory");
}
__device__ __forceinline__ void cp_commit() {
    asm volatile("cp.async.commit_group;" ::: "memory");
}
template <int N>
__device__ __forceinline__ void cp_wait() {
    asm volatile("cp.async.wait_group %0;" :: "n"(N) : "memory");
}
__device__ __forceinline__ void ldsm4(uint32_t& r0, uint32_t& r1, uint32_t& r2,
                                      uint32_t& r3, uint32_t addr) {
    asm volatile("ldmatrix.sync.aligned.m8n8.x4.shared.b16 {%0,%1,%2,%3}, [%4];"
                 : "=r"(r0), "=r"(r1), "=r"(r2), "=r"(r3) : "r"(addr));
}
__device__ __forceinline__ void mma16(float* c, const uint32_t* a, const uint32_t* b) {
    asm volatile("mma.sync.aligned.m16n8k16.row.col.f32.f16.f16.f32 "
                 "{%0,%1,%2,%3},{%4,%5,%6,%7},{%8,%9},{%0,%1,%2,%3};"
                 : "+f"(c[0]), "+f"(c[1]), "+f"(c[2]), "+f"(c[3])
                 : "r"(a[0]), "r"(a[1]), "r"(a[2]), "r"(a[3]),
                   "r"(b[0]), "r"(b[1]));
}

// ============== prep: fp16 conversions + pre-swizzled W images ==============
__global__ void prep_kernel(const float* __restrict__ x,  const float* __restrict__ Wb,
                            const float* __restrict__ W1, const float* __restrict__ W2)
{
    const int tid = blockIdx.x * blockDim.x + threadIdx.x;
    const int nth = gridDim.x * blockDim.x;

    for (int i = tid; i < XN / 8; i += nth) {
        const float4* src = (const float4*)x + (size_t)i * 2;
        float4 v0 = src[0], v1 = src[1];
        ((uint4*)g_xh)[i] = make_uint4(h2u(__floats2half2_rn(v0.x, v0.y)),
                                       h2u(__floats2half2_rn(v0.z, v0.w)),
                                       h2u(__floats2half2_rn(v1.x, v1.y)),
                                       h2u(__floats2half2_rn(v1.z, v1.w)));
    }
    for (int i = tid; i < WBN / 8; i += nth) {
        const float4* src = (const float4*)Wb + (size_t)i * 2;
        float4 v0 = src[0], v1 = src[1];
        ((uint4*)g_wbh)[i] = make_uint4(h2u(__floats2half2_rn(v0.x, v0.y)),
                                        h2u(__floats2half2_rn(v0.z, v0.w)),
                                        h2u(__floats2half2_rn(v1.x, v1.y)),
                                        h2u(__floats2half2_rn(v1.z, v1.w)));
    }
    // W1 [s][c][h] -> image [h][c] swizzled; 8 c-values per 16B store.
    for (int i = tid; i < 64 * 1024; i += nth) {
        int s = i >> 10, c8 = (i >> 7) & 7, h = i & 127;
        const float* src = W1 + (((size_t)s * 64 + c8 * 8) * 128 + h);
        uint32_t p[4];
        #pragma unroll
        for (int j = 0; j < 4; j++)
            p[j] = h2u(__floats2half2_rn(src[(2*j) * 128], src[(2*j+1) * 128]));
        int off = h * 64 + ((c8 ^ (h & 7)) << 3);
        *(uint4*)(g_w1img + (size_t)s * 8192 + off) = make_uint4(p[0], p[1], p[2], p[3]);
    }
    // W2 [s][h][c] -> image [c][h] swizzled; 8 h-values per 16B store.
    for (int i = tid; i < 64 * 1024; i += nth) {
        int s = i >> 10, h8 = (i >> 6) & 15, c = i & 63;
        const float* src = W2 + (((size_t)s * 128 + h8 * 8) * 64 + c);
        uint32_t p[4];
        #pragma unroll
        for (int j = 0; j < 4; j++)
            p[j] = h2u(__floats2half2_rn(src[(2*j) * 64], src[(2*j+1) * 64]));
        int off = c * 128 + ((h8 ^ (c & 7)) << 3);
        *(uint4*)(g_w2img + (size_t)s * 8192 + off) = make_uint4(p[0], p[1], p[2], p[3]);
    }
}

// stage one k-tile (k=64): x[128x64]h + wb[128x64]h, both 16KB, 128B rows
__device__ __forceinline__ void issue_tile(uint32_t su, const __half* xg,
                                           const __half* wbg, int kt, int b, int tid)
{
    const int k0 = kt * 64;
    #pragma unroll
    for (int i = 0; i < 4; i++) {
        int idx = tid + i * NTH;
        int r = idx >> 3, c4 = idx & 7;
        cpa16(su + BUF(b) + r * 128 + ((c4 ^ (r & 7)) << 4),
              xg + (size_t)r * D_IN + k0 + c4 * 8);
    }
    #pragma unroll
    for (int i = 0; i < 4; i++) {
        int idx = tid + i * NTH;
        int n = idx >> 3, c4 = idx & 7;
        cpa16(su + BUF(b) + 16384 + n * 128 + ((c4 ^ (n & 7)) << 4),
              wbg + (size_t)n * D_IN + k0 + c4 * 8);
    }
}

// 16KB image loads (1024 x 16B chunks, 4 per thread)
__device__ __forceinline__ void issue_w1(uint32_t su, int sg, int tid) {
    const __half* src = g_w1img + (size_t)sg * 8192;
    #pragma unroll
    for (int i = 0; i < 4; i++) {
        int c = tid + i * NTH;
        cpa16(su + W_OFF + c * 16, src + c * 8);
    }
}
__device__ __forceinline__ void issue_w2(uint32_t su, int sg, int tid) {
    const __half* src = g_w2img + (size_t)sg * 8192;
    #pragma unroll
    for (int i = 0; i < 4; i++) {
        int c = tid + i * NTH;
        cpa16(su + W_OFF + 16384 + c * 16, src + c * 8);
    }
}

__global__ __launch_bounds__(NTH, 2)
void kasmina_main_kernel(const float* __restrict__ bb,
                         const float* __restrict__ b1,
                         const float* __restrict__ b2,
                         const float* __restrict__ alpha,
                         const int*   __restrict__ active,
                         float* __restrict__ out)
{
    extern __shared__ char smem[];
    const uint32_t su = (uint32_t)__cvta_generic_to_shared(smem);
    float* bbs = (float*)(smem + BBS_OFF);

    const int bx   = blockIdx.x;          // out cols [bx*128, bx*128+128)
    const int row0 = blockIdx.y * 128;

    const int tid    = threadIdx.x;
    const int lane   = tid & 31;
    const int wid    = tid >> 5;
    const int warp_m = wid & 1;
    const int warp_n = wid >> 1;

    const __half* xg  = g_xh  + (size_t)row0 * D_IN;
    const __half* wbg = g_wbh + (size_t)(bx * 128) * D_IN;

    if (tid < 128) bbs[tid] = bb[bx * 128 + tid];

    // per-CTA-uniform blend weights
    const float aw0 = alpha[bx * 2]     * (active[bx * 2]     != 0 ? 1.f : 0.f);
    const float aw1 = alpha[bx * 2 + 1] * (active[bx * 2 + 1] != 0 ? 1.f : 0.f);

    // prologue: tiles 0,1
    issue_tile(su, xg, wbg, 0, 0, tid);  cp_commit();
    issue_tile(su, xg, wbg, 1, 1, tid);  cp_commit();

    // ================= base GEMM: 16 k-tiles, 3-buffer, 1 barrier/tile =================
    // PROVEN ORDERING (r8): cp_wait -> __syncthreads -> issue next.
    float acc[4][4][4];
    #pragma unroll
    for (int mt = 0; mt < 4; mt++)
        #pragma unroll
        for (int nt = 0; nt < 4; nt++)
            #pragma unroll
            for (int q = 0; q < 4; q++) acc[mt][nt][q] = 0.f;

    int bc = 0, bw = 2;   // compute buf, write buf (mod-3 counters)
    #pragma unroll 1
    for (int ks = 0; ks < 16; ks++) {
        cp_wait<1>();      // this thread's share of tile ks landed
        __syncthreads();   // all threads' waits done -> tile ks visible to all;
                           // + every warp finished reading buf bw (iter ks-1)
        if (ks + 2 < 16) issue_tile(su, xg, wbg, ks + 2, bw, tid);
        cp_commit();

        const uint32_t xs  = su + BUF(bc);
        const uint32_t wbs = xs + 16384;
        #pragma unroll
        for (int kk = 0; kk < 4; kk++) {
            uint32_t a[4][4], b[4][2];
            #pragma unroll
            for (int mt = 0; mt < 4; mt++) {
                int row = warp_m * 64 + mt * 16 + ((lane >> 3) & 1) * 8 + (lane & 7);
                int ch  = kk * 2 + (lane >> 4);
                ldsm4(a[mt][0], a[mt][1], a[mt][2], a[mt][3],
                      xs + row * 128 + ((ch ^ (row & 7)) << 4));
            }
            #pragma unroll
            for (int p = 0; p < 2; p++) {
                int row = warp_n * 32 + p * 16 + (lane >> 4) * 8 + (lane & 7);
                int ch  = kk * 2 + ((lane >> 3) & 1);
                ldsm4(b[2*p][0], b[2*p][1], b[2*p+1][0], b[2*p+1][1],
                      wbs + row * 128 + ((ch ^ (row & 7)) << 4));
            }
            #pragma unroll
            for (int mt = 0; mt < 4; mt++)
                #pragma unroll
                for (int nt = 0; nt < 4; nt++)
                    mma16(acc[mt][nt], a[mt], b[nt]);
        }
        bc = (bc == 2) ? 0 : bc + 1;
        bw = (bw == 2) ? 0 : bw + 1;
    }
    __syncthreads();   // all warps past compute(15); buf0/buf2 free for reuse

    // prefetch W images for the FIRST ACTIVE seed only (uniform per CTA)
    const int first_act = (aw0 != 0.f) ? 0 : ((aw1 != 0.f) ? 1 : -1);
    if (first_act >= 0) {
        issue_w1(su, bx * 2 + first_act, tid);
        issue_w2(su, bx * 2 + first_act, tid);
        cp_commit();
    }

    // epilogue: per seed-half (sl = warp_n>>1, UNIFORM per warp):
    //   active   -> y+bb as fp16 into ysw (for stage A + blend)
    //   inactive -> y+bb stored fp32 DIRECTLY to out (exact passthrough)
    {
        const int  sl_w   = warp_n >> 1;
        const bool act_w  = (sl_w == 0) ? (aw0 != 0.f) : (aw1 != 0.f);
        #pragma unroll
        for (int mt = 0; mt < 4; mt++) {
            #pragma unroll
            for (int nt = 0; nt < 4; nt++) {
                int c0 = warp_n * 32 + nt * 8 + 2 * (lane & 3);
                int r0 = warp_m * 64 + mt * 16 + (lane >> 2);
                float bx0 = bbs[c0], bx1 = bbs[c0 + 1];
                float v00 = acc[mt][nt][0] + bx0, v01 = acc[mt][nt][1] + bx1;
                float v10 = acc[mt][nt][2] + bx0, v11 = acc[mt][nt][3] + bx1;
                if (act_w) {
                    uint32_t sw0 = (((c0 >> 3) ^ (r0 & 7)) << 4) + ((c0 * 2) & 15);
                    uint32_t sw1 = (((c0 >> 3) ^ ((r0 + 8) & 7)) << 4) + ((c0 * 2) & 15);
                    *(uint32_t*)(smem + YSW_OFF + r0 * 256 + sw0) =
                        h2u(__floats2half2_rn(v00, v01));
                    *(uint32_t*)(smem + YSW_OFF + (r0 + 8) * 256 + sw1) =
                        h2u(__floats2half2_rn(v10, v11));
                } else {
                    *(float2*)&out[(size_t)(row0 + r0) * D_OUT + bx * 128 + c0] =
                        make_float2(v00, v01);
                    *(float2*)&out[(size_t)(row0 + r0 + 8) * D_OUT + bx * 128 + c0] =
                        make_float2(v10, v11);
                }
            }
        }
    }
    if (first_act < 0) return;   // both seeds inactive: CTA done (uniform)

    cp_wait<0>();      // first active seed's W images resident (this thread)
    __syncthreads();   // all threads' waits done; ysw + W visible everywhere

    const uint32_t ysw_b = su + YSW_OFF;
    const uint32_t h_b   = su + H_OFF;
    const uint32_t w1b   = su + W_OFF;
    const uint32_t w2b   = su + W_OFF + 16384;

    // ================= per-seed MLP + blend (active seeds only) =================
    #pragma unroll 1
    for (int sl = 0; sl < 2; sl++) {
        const float aw = (sl == 0) ? aw0 : aw1;
        if (aw == 0.f) continue;                 // uniform per CTA
        const int   sg  = bx * 2 + sl;
        const float omw = 1.f - aw;

        if (sl == 1 && aw0 != 0.f) {   // seed-1 W issued during seed-0 stage B
            cp_wait<0>();
            __syncthreads();
        }

        // ---- stage A: h = relu(y @ W1 + b1)   M=128 N=128 K=64 ----
        {
            float accA[4][4][4];
            #pragma unroll
            for (int mt = 0; mt < 4; mt++)
                #pragma unroll
                for (int nt = 0; nt < 4; nt++)
                    #pragma unroll
                    for (int q = 0; q < 4; q++) accA[mt][nt][q] = 0.f;

            #pragma unroll
            for (int kk = 0; kk < 4; kk++) {
                uint32_t a[4][4], b[4][2];
                #pragma unroll
                for (int mt = 0; mt < 4; mt++) {
                    int row = warp_m * 64 + mt * 16 + ((lane >> 3) & 1) * 8 + (lane & 7);
                    int ch  = sl * 8 + kk * 2 + (lane >> 4);
                    ldsm4(a[mt][0], a[mt][1], a[mt][2], a[mt][3],
                          ysw_b + row * 256 + ((ch ^ (row & 7)) << 4));
                }
                #pragma unroll
                for (int p = 0; p < 2; p++) {
                    int row = warp_n * 32 + p * 16 + (lane >> 4) * 8 + (lane & 7);
                    int ch  = kk * 2 + ((lane >> 3) & 1);
                    ldsm4(b[2*p][0], b[2*p][1], b[2*p+1][0], b[2*p+1][1],
                          w1b + row * 128 + ((ch ^ (row & 7)) << 4));
                }
                #pragma unroll
                for (int mt = 0; mt < 4; mt++)
                    #pragma unroll
                    for (int nt = 0; nt < 4; nt++)
                        mma16(accA[mt][nt], a[mt], b[nt]);
            }

            // bias + relu -> h (fp16 swizzled, buf1)
            #pragma unroll
            for (int mt = 0; mt < 4; mt++) {
                #pragma unroll
                for (int nt = 0; nt < 4; nt++) {
                    int h0 = warp_n * 32 + nt * 8 + 2 * (lane & 3);
                    int r0 = warp_m * 64 + mt * 16 + (lane >> 2);
                    float2 b1v = *(const float2*)&b1[sg * 128 + h0];
                    float v0 = fmaxf(accA[mt][nt][0] + b1v.x, 0.f);
                    float v1 = fmaxf(accA[mt][nt][1] + b1v.y, 0.f);
                    float v2 = fmaxf(accA[mt][nt][2] + b1v.x, 0.f);
                    float v3 = fmaxf(accA[mt][nt][3] + b1v.y, 0.f);
                    uint32_t sw0 = (((h0 >> 3) ^ (r0 & 7)) << 4) + ((h0 * 2) & 15);
                    uint32_t sw1 = (((h0 >> 3) ^ ((r0 + 8) & 7)) << 4) + ((h0 * 2) & 15);
                    *(uint32_t*)(smem + H_OFF + r0 * 256 + sw0) =
                        h2u(__floats2half2_rn(v0, v1));
                    *(uint32_t*)(smem + H_OFF + (r0 + 8) * 256 + sw1) =
                        h2u(__floats2half2_rn(v2, v3));
                }
            }
        }
        __syncthreads();   // h visible

        // ---- stage B: bp = h @ W2 + b2; blend with fp16 y; store ----
        {
            float accB[4][2][4];
            #pragma unroll
            for (int mt = 0; mt < 4; mt++)
                #pragma unroll
                for (int nt = 0; nt < 2; nt++)
                    #pragma unroll
                    for (int q = 0; q < 4; q++) accB[mt][nt][q] = 0.f;

            #pragma unroll 4
            for (int kk = 0; kk < 8; kk++) {
                uint32_t a[4][4], b[2][2];
                #pragma unroll
                for (int mt = 0; mt < 4; mt++) {
                    int row = warp_m * 64 + mt * 16 + ((lane >> 3) & 1) * 8 + (lane & 7);
                    int ch  = kk * 2 + (lane >> 4);
                    ldsm4(a[mt][0], a[mt][1], a[mt][2], a[mt][3],
                          h_b + row * 256 + ((ch ^ (row & 7)) << 4));
                }
                {
                    int row = warp_n * 16 + (lane >> 4) * 8 + (lane & 7);
                    int ch  = kk * 2 + ((lane >> 3) & 1);
                    ldsm4(b[0][0], b[0][1], b[1][0], b[1][1],
                          w2b + row * 256 + ((ch ^ (row & 7)) << 4));
                }
                #pragma unroll
                for (int mt = 0; mt < 4; mt++)
                    #pragma unroll
                    for (int nt = 0; nt < 2; nt++)
                        mma16(accB[mt][nt], a[mt], b[nt]);
            }

            #pragma unroll
            for (int mt = 0; mt < 4; mt++) {
                #pragma unroll
                for (int nt = 0; nt < 2; nt++) {
                    int c0 = warp_n * 16 + nt * 8 + 2 * (lane & 3);
                    int cy = sl * 64 + c0;
                    int r0 = warp_m * 64 + mt * 16 + (lane >> 2);
                    float2 b2v = *(const float2*)&b2[sg * 64 + c0];

                    __half2 hy0 = *(const __half2*)(smem + YSW_OFF + r0 * 256 +
                                   (((cy >> 3) ^ (r0 & 7)) << 4) + ((cy * 2) & 15));
                    float2 y0 = __half22float2(hy0);
                    *(float2*)&out[(size_t)(row0 + r0) * D_OUT + bx * 128 + cy] =
                        make_float2(omw * y0.x + aw * (accB[mt][nt][0] + b2v.x),
                                    omw * y0.y + aw * (accB[mt][nt][1] + b2v.y));

                    __half2 hy1 = *(const __half2*)(smem + YSW_OFF + (r0 + 8) * 256 +
                                   (((cy >> 3) ^ ((r0 + 8) & 7)) << 4) + ((cy * 2) & 15));
                    float2 y1 = __half22float2(hy1);
                    *(float2*)&out[(size_t)(row0 + r0 + 8) * D_OUT + bx * 128 + cy] =
                        make_float2(omw * y1.x + aw * (accB[mt][nt][2] + b2v.x),
                                    omw * y1.y + aw * (accB[mt][nt][3] + b2v.y));
                }
            }
        }

        if (sl == 0 && aw1 != 0.f) {   // uniform condition; barrier is CTA-wide
            __syncthreads();           // W/h reads complete before overwrite
            issue_w1(su, sg + 1, tid);
            issue_w2(su, sg + 1, tid);
            cp_commit();
        }
    }
}

extern "C" void kernel_launch(void* const* d_in, const int* in_sizes, int n_in,
                              void* d_out, int out_size)
{
    const float* x      = (const float*)d_in[0];
    const float* Wb     = (const float*)d_in[1];
    const float* bb     = (const float*)d_in[2];
    const float* W1     = (const float*)d_in[3];
    const float* b1     = (const float*)d_in[4];
    const float* W2     = (const float*)d_in[5];
    const float* b2     = (const float*)d_in[6];
    const float* alpha  = (const float*)d_in[7];
    const int*   active = (const int*)d_in[8];
    float* out = (float*)d_out;

    prep_kernel<<<1024, 256>>>(x, Wb, W1, W2);

    cudaFuncSetAttribute(kasmina_main_kernel,
                         cudaFuncAttributeMaxDynamicSharedMemorySize, SMEM_TOTAL);
    dim3 grid(32, 64);
    kasmina_main_kernel<<<grid, NTH, SMEM_TOTAL>>>(
        bb, b1, b2, alpha, active, out);
}

// round 16
// speedup vs baseline: 1.0983x; 1.0074x over previous
#include <cuda_runtime.h>
#include <cuda_fp16.h>
#include <cstdint>

#define NTH    256
#define D_IN   1024
#define D_OUT  4096
#define XN     (8192 * 1024)
#define WBN    (4096 * 1024)

__device__ __half g_xh[XN];           // x  as fp16
__device__ __half g_wbh[WBN];         // Wb as fp16
__device__ __half g_w1img[64 * 8192]; // W1 pre-swizzled smem images (16KB/seed)
__device__ __half g_w2img[64 * 8192]; // W2 pre-swizzled smem images

// ---------------- smem layout (bytes), CTA tile 128 x 128 (r12/r15 proven) --------
// phase 1: 3 staging buffers 32KB (x 16KB + wb 16KB each), k-tile=64
// phase 2 overlays staging:
//   ysw fp16 [128][128] swz  buf0:      0 .. 32767
//   h   fp16 [128][128] swz  buf1:  32768 .. 65535
//   W   (W1 16KB + W2 16KB)  buf2:  65536 .. 98303
//   bbs fp32 [128]                  98304 .. 98815
#define BUF(i)   ((i) * 32768)
#define YSW_OFF  0
#define H_OFF    32768
#define W_OFF    65536
#define BBS_OFF  98304
#define SMEM_TOTAL 98816

__device__ __forceinline__ uint32_t h2u(__half2 h) {
    return *reinterpret_cast<uint32_t*>(&h);
}
__device__ __forceinline__ void cpa16(uint32_t dst, const void* src) {
    asm volatile("cp.async.cg.shared.global [%0], [%1], 16;"
                 :: "r"(dst), "l"(src) : "memory");
}
__device__ __forceinline__ void cp_commit() {
    asm volatile("cp.async.commit_group;" ::: "memory");
}
template <int N>
__device__ __forceinline__ void cp_wait() {
    asm volatile("cp.async.wait_group %0;" :: "n"(N) : "memory");
}
__device__ __forceinline__ void ldsm4(uint32_t& r0, uint32_t& r1, uint32_t& r2,
                                      uint32_t& r3, uint32_t addr) {
    asm volatile("ldmatrix.sync.aligned.m8n8.x4.shared.b16 {%0,%1,%2,%3}, [%4];"
                 : "=r"(r0), "=r"(r1), "=r"(r2), "=r"(r3) : "r"(addr));
}
__device__ __forceinline__ void mma16(float* c, const uint32_t* a, const uint32_t* b) {
    asm volatile("mma.sync.aligned.m16n8k16.row.col.f32.f16.f16.f32 "
                 "{%0,%1,%2,%3},{%4,%5,%6,%7},{%8,%9},{%0,%1,%2,%3};"
                 : "+f"(c[0]), "+f"(c[1]), "+f"(c[2]), "+f"(c[3])
                 : "r"(a[0]), "r"(a[1]), "r"(a[2]), "r"(a[3]),
                   "r"(b[0]), "r"(b[1]));
}

// ============== prep: fp16 conversions + pre-swizzled W images ==============
__global__ void prep_kernel(const float* __restrict__ x,  const float* __restrict__ Wb,
                            const float* __restrict__ W1, const float* __restrict__ W2)
{
    const int tid = blockIdx.x * blockDim.x + threadIdx.x;
    const int nth = gridDim.x * blockDim.x;

    for (int i = tid; i < XN / 8; i += nth) {
        const float4* src = (const float4*)x + (size_t)i * 2;
        float4 v0 = src[0], v1 = src[1];
        ((uint4*)g_xh)[i] = make_uint4(h2u(__floats2half2_rn(v0.x, v0.y)),
                                       h2u(__floats2half2_rn(v0.z, v0.w)),
                                       h2u(__floats2half2_rn(v1.x, v1.y)),
                                       h2u(__floats2half2_rn(v1.z, v1.w)));
    }
    for (int i = tid; i < WBN / 8; i += nth) {
        const float4* src = (const float4*)Wb + (size_t)i * 2;
        float4 v0 = src[0], v1 = src[1];
        ((uint4*)g_wbh)[i] = make_uint4(h2u(__floats2half2_rn(v0.x, v0.y)),
                                        h2u(__floats2half2_rn(v0.z, v0.w)),
                                        h2u(__floats2half2_rn(v1.x, v1.y)),
                                        h2u(__floats2half2_rn(v1.z, v1.w)));
    }
    // W1 [s][c][h] -> image [h][c] swizzled; 8 c-values per 16B store.
    for (int i = tid; i < 64 * 1024; i += nth) {
        int s = i >> 10, c8 = (i >> 7) & 7, h = i & 127;
        const float* src = W1 + (((size_t)s * 64 + c8 * 8) * 128 + h);
        uint32_t p[4];
        #pragma unroll
        for (int j = 0; j < 4; j++)
            p[j] = h2u(__floats2half2_rn(src[(2*j) * 128], src[(2*j+1) * 128]));
        int off = h * 64 + ((c8 ^ (h & 7)) << 3);
        *(uint4*)(g_w1img + (size_t)s * 8192 + off) = make_uint4(p[0], p[1], p[2], p[3]);
    }
    // W2 [s][h][c] -> image [c][h] swizzled; 8 h-values per 16B store.
    for (int i = tid; i < 64 * 1024; i += nth) {
        int s = i >> 10, h8 = (i >> 6) & 15, c = i & 63;
        const float* src = W2 + (((size_t)s * 128 + h8 * 8) * 64 + c);
        uint32_t p[4];
        #pragma unroll
        for (int j = 0; j < 4; j++)
            p[j] = h2u(__floats2half2_rn(src[(2*j) * 64], src[(2*j+1) * 64]));
        int off = c * 128 + ((h8 ^ (c & 7)) << 3);
        *(uint4*)(g_w2img + (size_t)s * 8192 + off) = make_uint4(p[0], p[1], p[2], p[3]);
    }
}

// stage one k-tile (k=64): x[128x64]h + wb[128x64]h, both 16KB, 128B rows
__device__ __forceinline__ void issue_tile(uint32_t su, const __half* xg,
                                           const __half* wbg, int kt, int b, int tid)
{
    const int k0 = kt * 64;
    #pragma unroll
    for (int i = 0; i < 4; i++) {
        int idx = tid + i * NTH;
        int r = idx >> 3, c4 = idx & 7;
        cpa16(su + BUF(b) + r * 128 + ((c4 ^ (r & 7)) << 4),
              xg + (size_t)r * D_IN + k0 + c4 * 8);
    }
    #pragma unroll
    for (int i = 0; i < 4; i++) {
        int idx = tid + i * NTH;
        int n = idx >> 3, c4 = idx & 7;
        cpa16(su + BUF(b) + 16384 + n * 128 + ((c4 ^ (n & 7)) << 4),
              wbg + (size_t)n * D_IN + k0 + c4 * 8);
    }
}

// 16KB image loads (1024 x 16B chunks, 4 per thread)
__device__ __forceinline__ void issue_w1(uint32_t su, int sg, int tid) {
    const __half* src = g_w1img + (size_t)sg * 8192;
    #pragma unroll
    for (int i = 0; i < 4; i++) {
        int c = tid + i * NTH;
        cpa16(su + W_OFF + c * 16, src + c * 8);
    }
}
__device__ __forceinline__ void issue_w2(uint32_t su, int sg, int tid) {
    const __half* src = g_w2img + (size_t)sg * 8192;
    #pragma unroll
    for (int i = 0; i < 4; i++) {
        int c = tid + i * NTH;
        cpa16(su + W_OFF + 16384 + c * 16, src + c * 8);
    }
}

__global__ __launch_bounds__(NTH, 2)
void kasmina_main_kernel(const float* __restrict__ bb,
                         const float* __restrict__ b1,
                         const float* __restrict__ b2,
                         const float* __restrict__ alpha,
                         const int*   __restrict__ active,
                         float* __restrict__ out)
{
    extern __shared__ char smem[];
    const uint32_t su = (uint32_t)__cvta_generic_to_shared(smem);
    float* bbs = (float*)(smem + BBS_OFF);

    const int bx   = blockIdx.x;          // out cols [bx*128, bx*128+128)
    const int row0 = blockIdx.y * 128;

    const int tid    = threadIdx.x;
    const int lane   = tid & 31;
    const int wid    = tid >> 5;
    const int warp_m = wid & 1;
    const int warp_n = wid >> 1;

    const __half* xg  = g_xh  + (size_t)row0 * D_IN;
    const __half* wbg = g_wbh + (size_t)(bx * 128) * D_IN;

    if (tid < 128) bbs[tid] = bb[bx * 128 + tid];

    // per-CTA-uniform blend weights
    const float aw0 = alpha[bx * 2]     * (active[bx * 2]     != 0 ? 1.f : 0.f);
    const float aw1 = alpha[bx * 2 + 1] * (active[bx * 2 + 1] != 0 ? 1.f : 0.f);

    // prologue: tiles 0,1
    issue_tile(su, xg, wbg, 0, 0, tid);  cp_commit();
    issue_tile(su, xg, wbg, 1, 1, tid);  cp_commit();

    // ================= base GEMM: 16 k-tiles, 3-buffer, 1 barrier/tile =================
    // PROVEN ORDERING (r8): cp_wait -> __syncthreads. kk=0 compute is PEELED to
    // run before the next tile's cp.async issue burst (volatile asm order is
    // final -> compute starts immediately after the barrier; LSU burst overlaps
    // kk=1..3 MMAs instead of delaying kk=0).
    float acc[4][4][4];
    #pragma unroll
    for (int mt = 0; mt < 4; mt++)
        #pragma unroll
        for (int nt = 0; nt < 4; nt++)
            #pragma unroll
            for (int q = 0; q < 4; q++) acc[mt][nt][q] = 0.f;

    int bc = 0, bw = 2;   // compute buf, write buf (mod-3 counters)
    #pragma unroll 1
    for (int ks = 0; ks < 16; ks++) {
        cp_wait<1>();      // this thread's share of tile ks landed
        __syncthreads();   // all threads' waits done -> tile ks visible to all;
                           // + every warp finished reading buf bw (iter ks-1)
        const uint32_t xs  = su + BUF(bc);
        const uint32_t wbs = xs + 16384;

        // ---- kk = 0 (peeled: fragments + MMAs before the issue burst) ----
        {
            uint32_t a[4][4], b[4][2];
            #pragma unroll
            for (int mt = 0; mt < 4; mt++) {
                int row = warp_m * 64 + mt * 16 + ((lane >> 3) & 1) * 8 + (lane & 7);
                int ch  = lane >> 4;
                ldsm4(a[mt][0], a[mt][1], a[mt][2], a[mt][3],
                      xs + row * 128 + ((ch ^ (row & 7)) << 4));
            }
            #pragma unroll
            for (int p = 0; p < 2; p++) {
                int row = warp_n * 32 + p * 16 + (lane >> 4) * 8 + (lane & 7);
                int ch  = (lane >> 3) & 1;
                ldsm4(b[2*p][0], b[2*p][1], b[2*p+1][0], b[2*p+1][1],
                      wbs + row * 128 + ((ch ^ (row & 7)) << 4));
            }
            #pragma unroll
            for (int mt = 0; mt < 4; mt++)
                #pragma unroll
                for (int nt = 0; nt < 4; nt++)
                    mma16(acc[mt][nt], a[mt], b[nt]);
        }

        // issue next tile (overlaps kk=1..3 compute)
        if (ks + 2 < 16) issue_tile(su, xg, wbg, ks + 2, bw, tid);
        cp_commit();

        // ---- kk = 1..3 ----
        #pragma unroll
        for (int kk = 1; kk < 4; kk++) {
            uint32_t a[4][4], b[4][2];
            #pragma unroll
            for (int mt = 0; mt < 4; mt++) {
                int row = warp_m * 64 + mt * 16 + ((lane >> 3) & 1) * 8 + (lane & 7);
                int ch  = kk * 2 + (lane >> 4);
                ldsm4(a[mt][0], a[mt][1], a[mt][2], a[mt][3],
                      xs + row * 128 + ((ch ^ (row & 7)) << 4));
            }
            #pragma unroll
            for (int p = 0; p < 2; p++) {
                int row = warp_n * 32 + p * 16 + (lane >> 4) * 8 + (lane & 7);
                int ch  = kk * 2 + ((lane >> 3) & 1);
                ldsm4(b[2*p][0], b[2*p][1], b[2*p+1][0], b[2*p+1][1],
                      wbs + row * 128 + ((ch ^ (row & 7)) << 4));
            }
            #pragma unroll
            for (int mt = 0; mt < 4; mt++)
                #pragma unroll
                for (int nt = 0; nt < 4; nt++)
                    mma16(acc[mt][nt], a[mt], b[nt]);
        }
        bc = (bc == 2) ? 0 : bc + 1;
        bw = (bw == 2) ? 0 : bw + 1;
    }
    __syncthreads();   // all warps past compute(15); buf0/buf2 free for reuse

    // prefetch W images for the FIRST ACTIVE seed only (uniform per CTA)
    const int first_act = (aw0 != 0.f) ? 0 : ((aw1 != 0.f) ? 1 : -1);
    if (first_act >= 0) {
        issue_w1(su, bx * 2 + first_act, tid);
        issue_w2(su, bx * 2 + first_act, tid);
        cp_commit();
    }

    // epilogue: per seed-half (sl = warp_n>>1, UNIFORM per warp):
    //   active   -> y+bb as fp16 into ysw (for stage A + blend)
    //   inactive -> y+bb stored fp32 DIRECTLY to out (exact passthrough)
    {
        const int  sl_w   = warp_n >> 1;
        const bool act_w  = (sl_w == 0) ? (aw0 != 0.f) : (aw1 != 0.f);
        #pragma unroll
        for (int mt = 0; mt < 4; mt++) {
            #pragma unroll
            for (int nt = 0; nt < 4; nt++) {
                int c0 = warp_n * 32 + nt * 8 + 2 * (lane & 3);
                int r0 = warp_m * 64 + mt * 16 + (lane >> 2);
                float bx0 = bbs[c0], bx1 = bbs[c0 + 1];
                float v00 = acc[mt][nt][0] + bx0, v01 = acc[mt][nt][1] + bx1;
                float v10 = acc[mt][nt][2] + bx0, v11 = acc[mt][nt][3] + bx1;
                if (act_w) {
                    uint32_t sw0 = (((c0 >> 3) ^ (r0 & 7)) << 4) + ((c0 * 2) & 15);
                    uint32_t sw1 = (((c0 >> 3) ^ ((r0 + 8) & 7)) << 4) + ((c0 * 2) & 15);
                    *(uint32_t*)(smem + YSW_OFF + r0 * 256 + sw0) =
                        h2u(__floats2half2_rn(v00, v01));
                    *(uint32_t*)(smem + YSW_OFF + (r0 + 8) * 256 + sw1) =
                        h2u(__floats2half2_rn(v10, v11));
                } else {
                    *(float2*)&out[(size_t)(row0 + r0) * D_OUT + bx * 128 + c0] =
                        make_float2(v00, v01);
                    *(float2*)&out[(size_t)(row0 + r0 + 8) * D_OUT + bx * 128 + c0] =
                        make_float2(v10, v11);
                }
            }
        }
    }
    if (first_act < 0) return;   // both seeds inactive: CTA done (uniform)

    cp_wait<0>();      // first active seed's W images resident (this thread)
    __syncthreads();   // all threads' waits done; ysw + W visible everywhere

    const uint32_t ysw_b = su + YSW_OFF;
    const uint32_t h_b   = su + H_OFF;
    const uint32_t w1b   = su + W_OFF;
    const uint32_t w2b   = su + W_OFF + 16384;

    // ================= per-seed MLP + blend (active seeds only) =================
    #pragma unroll 1
    for (int sl = 0; sl < 2; sl++) {
        const float aw = (sl == 0) ? aw0 : aw1;
        if (aw == 0.f) continue;                 // uniform per CTA
        const int   sg  = bx * 2 + sl;
        const float omw = 1.f - aw;

        if (sl == 1 && aw0 != 0.f) {   // seed-1 W issued during seed-0 stage B
            cp_wait<0>();
            __syncthreads();
        }

        // ---- stage A: h = relu(y @ W1 + b1)   M=128 N=128 K=64 ----
        {
            float accA[4][4][4];
            #pragma unroll
            for (int mt = 0; mt < 4; mt++)
                #pragma unroll
                for (int nt = 0; nt < 4; nt++)
                    #pragma unroll
                    for (int q = 0; q < 4; q++) accA[mt][nt][q] = 0.f;

            #pragma unroll
            for (int kk = 0; kk < 4; kk++) {
                uint32_t a[4][4], b[4][2];
                #pragma unroll
                for (int mt = 0; mt < 4; mt++) {
                    int row = warp_m * 64 + mt * 16 + ((lane >> 3) & 1) * 8 + (lane & 7);
                    int ch  = sl * 8 + kk * 2 + (lane >> 4);
                    ldsm4(a[mt][0], a[mt][1], a[mt][2], a[mt][3],
                          ysw_b + row * 256 + ((ch ^ (row & 7)) << 4));
                }
                #pragma unroll
                for (int p = 0; p < 2; p++) {
                    int row = warp_n * 32 + p * 16 + (lane >> 4) * 8 + (lane & 7);
                    int ch  = kk * 2 + ((lane >> 3) & 1);
                    ldsm4(b[2*p][0], b[2*p][1], b[2*p+1][0], b[2*p+1][1],
                          w1b + row * 128 + ((ch ^ (row & 7)) << 4));
                }
                #pragma unroll
                for (int mt = 0; mt < 4; mt++)
                    #pragma unroll
                    for (int nt = 0; nt < 4; nt++)
                        mma16(accA[mt][nt], a[mt], b[nt]);
            }

            // bias + relu -> h (fp16 swizzled, buf1)
            #pragma unroll
            for (int mt = 0; mt < 4; mt++) {
                #pragma unroll
                for (int nt = 0; nt < 4; nt++) {
                    int h0 = warp_n * 32 + nt * 8 + 2 * (lane & 3);
                    int r0 = warp_m * 64 + mt * 16 + (lane >> 2);
                    float2 b1v = *(const float2*)&b1[sg * 128 + h0];
                    float v0 = fmaxf(accA[mt][nt][0] + b1v.x, 0.f);
                    float v1 = fmaxf(accA[mt][nt][1] + b1v.y, 0.f);
                    float v2 = fmaxf(accA[mt][nt][2] + b1v.x, 0.f);
                    float v3 = fmaxf(accA[mt][nt][3] + b1v.y, 0.f);
                    uint32_t sw0 = (((h0 >> 3) ^ (r0 & 7)) << 4) + ((h0 * 2) & 15);
                    uint32_t sw1 = (((h0 >> 3) ^ ((r0 + 8) & 7)) << 4) + ((h0 * 2) & 15);
                    *(uint32_t*)(smem + H_OFF + r0 * 256 + sw0) =
                        h2u(__floats2half2_rn(v0, v1));
                    *(uint32_t*)(smem + H_OFF + (r0 + 8) * 256 + sw1) =
                        h2u(__floats2half2_rn(v2, v3));
                }
            }
        }
        __syncthreads();   // h visible

        // ---- stage B: bp = h @ W2 + b2; blend with fp16 y; store ----
        {
            float accB[4][2][4];
            #pragma unroll
            for (int mt = 0; mt < 4; mt++)
                #pragma unroll
                for (int nt = 0; nt < 2; nt++)
                    #pragma unroll
                    for (int q = 0; q < 4; q++) accB[mt][nt][q] = 0.f;

            #pragma unroll 4
            for (int kk = 0; kk < 8; kk++) {
                uint32_t a[4][4], b[2][2];
                #pragma unroll
                for (int mt = 0; mt < 4; mt++) {
                    int row = warp_m * 64 + mt * 16 + ((lane >> 3) & 1) * 8 + (lane & 7);
                    int ch  = kk * 2 + (lane >> 4);
                    ldsm4(a[mt][0], a[mt][1], a[mt][2], a[mt][3],
                          h_b + row * 256 + ((ch ^ (row & 7)) << 4));
                }
                {
                    int row = warp_n * 16 + (lane >> 4) * 8 + (lane & 7);
                    int ch  = kk * 2 + ((lane >> 3) & 1);
                    ldsm4(b[0][0], b[0][1], b[1][0], b[1][1],
                          w2b + row * 256 + ((ch ^ (row & 7)) << 4));
                }
                #pragma unroll
                for (int mt = 0; mt < 4; mt++)
                    #pragma unroll
                    for (int nt = 0; nt < 2; nt++)
                        mma16(accB[mt][nt], a[mt], b[nt]);
            }

            #pragma unroll
            for (int mt = 0; mt < 4; mt++) {
                #pragma unroll
                for (int nt = 0; nt < 2; nt++) {
                    int c0 = warp_n * 16 + nt * 8 + 2 * (lane & 3);
                    int cy = sl * 64 + c0;
                    int r0 = warp_m * 64 + mt * 16 + (lane >> 2);
                    float2 b2v = *(const float2*)&b2[sg * 64 + c0];

                    __half2 hy0 = *(const __half2*)(smem + YSW_OFF + r0 * 256 +
                                   (((cy >> 3) ^ (r0 & 7)) << 4) + ((cy * 2) & 15));
                    float2 y0 = __half22float2(hy0);
                    *(float2*)&out[(size_t)(row0 + r0) * D_OUT + bx * 128 + cy] =
                        make_float2(omw * y0.x + aw * (accB[mt][nt][0] + b2v.x),
                                    omw * y0.y + aw * (accB[mt][nt][1] + b2v.y));

                    __half2 hy1 = *(const __half2*)(smem + YSW_OFF + (r0 + 8) * 256 +
                                   (((cy >> 3) ^ ((r0 + 8) & 7)) << 4) + ((cy * 2) & 15));
                    float2 y1 = __half22float2(hy1);
                    *(float2*)&out[(size_t)(row0 + r0 + 8) * D_OUT + bx * 128 + cy] =
                        make_float2(omw * y1.x + aw * (accB[mt][nt][2] + b2v.x),
                                    omw * y1.y + aw * (accB[mt][nt][3] + b2v.y));
                }
            }
        }

        if (sl == 0 && aw1 != 0.f) {   // uniform condition; barrier is CTA-wide
            __syncthreads();           // W/h reads complete before overwrite
            issue_w1(su, sg + 1, tid);
            issue_w2(su, sg + 1, tid);
            cp_commit();
        }
    }
}

extern "C" void kernel_launch(void* const* d_in, const int* in_sizes, int n_in,
                              void* d_out, int out_size)
{
    const float* x      = (const float*)d_in[0];
    const float* Wb     = (const float*)d_in[1];
    const float* bb     = (const float*)d_in[2];
    const float* W1     = (const float*)d_in[3];
    const float* b1     = (const float*)d_in[4];
    const float* W2     = (const float*)d_in[5];
    const float* b2     = (const float*)d_in[6];
    const float* alpha  = (const float*)d_in[7];
    const int*   active = (const int*)d_in[8];
    float* out = (float*)d_out;

    prep_kernel<<<1024, 256>>>(x, Wb, W1, W2);

    cudaFuncSetAttribute(kasmina_main_kernel,
                         cudaFuncAttributeMaxDynamicSharedMemorySize, SMEM_TOTAL);
    dim3 grid(32, 64);
    kasmina_main_kernel<<<grid, NTH, SMEM_TOTAL>>>(
        bb, b1, b2, alpha, active, out);
}